// round 3
// baseline (speedup 1.0000x reference)
#include <cuda_runtime.h>
#include <cuda_bf16.h>

// Cascaded 16-tap FIR pair == single 33-tap causal conv for columns i >= 32:
//   y[i] = x[i] + sum_{j=1}^{32} g[j] * x[i-j],  g = [1,h] (*) [1,h_rev]
// Columns [0,32) computed exactly (v-mask aware) by threads 0-1 of block x=0.
//
// Inner loop uses packed fma.rn.f32x2: tap pairs (g[2m+2], g[2m+1]) against
// ascending data pairs (x[i-2m-2], x[i-2m-1]). Even outputs use b64-aligned
// pairs straight from the float4 loads; odd outputs use once-packed odd pairs.
//
// B=256 rows, N=131072 cols, F=16.

#define F       16
#define GT      33
#define THREADS 128
#define RPT     16
#define TILE    (THREADS * RPT)    // 2048
#define HALO    32
#define NCOL    131072
#define NROW    256

typedef unsigned long long u64;

#define FMA2(d, a, b, c) \
    asm("fma.rn.f32x2 %0, %1, %2, %3;" : "=l"(d) : "l"(a), "l"(b), "l"(c))
#define PACK2(p, lo, hi) \
    asm("mov.b64 %0, {%1, %2};" : "=l"(p) : "f"(lo), "f"(hi))
#define UNPACK2(lo, hi, p) \
    asm("mov.b64 {%0, %1}, %2;" : "=f"(lo), "=f"(hi) : "l"(p))

__global__ __launch_bounds__(THREADS, 3)
void fir2_fused(const float* __restrict__ x,
                const float* __restrict__ h,
                float* __restrict__ y)
{
    __shared__ float  sg[GT];
    __shared__ float2 sgp[F];      // sgp[m] = (g[2m+2], g[2m+1])

    const int tid = threadIdx.x;
    const int row = blockIdx.y;
    const int t0  = blockIdx.x * TILE;
    const size_t rowoff = (size_t)row * NCOL;

    // ---- per-block combined taps (threads 0..32) ---------------------------
    if (tid < GT) {
        const int j = tid;
        float acc = 0.0f;
        const int a0 = (j > F) ? (j - F) : 0;
        const int a1 = (j < F) ? j : F;
        for (int a = a0; a <= a1; a++) {
            const float ka = (a == 0) ? 1.0f : __ldg(h + a - 1);
            const int bb = j - a;
            const float kb = (bb == 0) ? 1.0f : __ldg(h + F - bb);
            acc += ka * kb;
        }
        sg[j] = acc;
    }
    __syncthreads();
    if (tid < F)
        sgp[tid] = make_float2(sg[2 * tid + 2], sg[2 * tid + 1]);
    __syncthreads();

    const bool edge = (blockIdx.x == 0) && (tid < 2);

    if (!edge) {
        // ---- window load: w[c] = x[row][base + c], c in [0,48) -------------
        const int base = t0 + tid * RPT - HALO;   // 128B-aligned, >= 0 here
        const float4* xp = reinterpret_cast<const float4*>(x + rowoff + base);

        u64 P[24];                 // P[c] = (w[2c], w[2c+1])  (b64-aligned pairs)
#pragma unroll
        for (int q = 0; q < 12; q++) {
            const ulonglong2 v = reinterpret_cast<const ulonglong2*>(xp)[q];
            P[2 * q]     = v.x;
            P[2 * q + 1] = v.y;
        }

        float wf[48];
#pragma unroll
        for (int c = 0; c < 24; c++) UNPACK2(wf[2 * c], wf[2 * c + 1], P[c]);

        u64 Q[23];                 // Q[c] = (w[2c+1], w[2c+2]) (odd-aligned pairs)
#pragma unroll
        for (int c = 0; c < 23; c++) PACK2(Q[c], wf[2 * c + 1], wf[2 * c + 2]);

        u64 gg[F];                 // packed tap pairs (broadcast LDS.64)
#pragma unroll
        for (int m = 0; m < F; m++)
            gg[m] = *reinterpret_cast<const u64*>(&sgp[m]);

        // ---- 16 outputs, 16 FFMA2 each -------------------------------------
        float out[RPT];
#pragma unroll
        for (int r = 0; r < RPT; r++) {
            u64 acc = 0;
            const int cb = (r >> 1) + 15;   // pair index for m = 0
            if ((r & 1) == 0) {
#pragma unroll
                for (int m = 0; m < F; m++) FMA2(acc, gg[m], P[cb - m], acc);
            } else {
#pragma unroll
                for (int m = 0; m < F; m++) FMA2(acc, gg[m], Q[cb - m], acc);
            }
            float alo, ahi;
            UNPACK2(alo, ahi, acc);
            out[r] = wf[r + HALO] + alo + ahi;
        }

        float4* yo = reinterpret_cast<float4*>(y + rowoff + t0 + tid * RPT);
#pragma unroll
        for (int q = 0; q < RPT / 4; q++)
            yo[q] = make_float4(out[4 * q], out[4 * q + 1],
                                out[4 * q + 2], out[4 * q + 3]);
    } else {
        // ---- exact masked two-stage result for columns [0,32) --------------
        if (tid == 0) {
            float4* yo = reinterpret_cast<float4*>(y + rowoff);
#pragma unroll
            for (int q = 0; q < 4; q++)
                yo[q] = make_float4(0.f, 0.f, 0.f, 0.f);   // y[0..15] = 0
        } else {
            const float* xr = x + rowoff;
            float xa[32];
#pragma unroll
            for (int c = 0; c < 32; c++) xa[c] = xr[c];
            float hh[F];
#pragma unroll
            for (int j = 0; j < F; j++) hh[j] = __ldg(h + j);

            float va[F];           // v[16..31]
#pragma unroll
            for (int t = 0; t < F; t++) {
                const int k = F + t;
                float acc = xa[k];
#pragma unroll
                for (int j = 0; j < F; j++)
                    acc = fmaf(hh[j], xa[k - 1 - j], acc);
                va[t] = acc;
            }
            float ya[F];           // y[16..31]
#pragma unroll
            for (int t = 0; t < F; t++) {
                const int i = F + t;
                float acc = va[t];
#pragma unroll
                for (int m = 0; m < F; m++) {
                    const int k = i - F + m;      // v index; masked if < 16
                    if (k >= F) acc = fmaf(hh[m], va[k - F], acc);
                }
                ya[t] = acc;
            }
            float4* yo = reinterpret_cast<float4*>(y + rowoff + F);
#pragma unroll
            for (int q = 0; q < 4; q++)
                yo[q] = make_float4(ya[4 * q], ya[4 * q + 1],
                                    ya[4 * q + 2], ya[4 * q + 3]);
        }
    }
}

extern "C" void kernel_launch(void* const* d_in, const int* in_sizes, int n_in,
                              void* d_out, int out_size)
{
    const float* x = (const float*)d_in[0];   // (256, 131072) f32
    const float* h = (const float*)d_in[1];   // (1, 16) f32
    float* y = (float*)d_out;                 // (256, 131072) f32

    dim3 grid(NCOL / TILE, NROW);
    fir2_fused<<<grid, THREADS>>>(x, h, y);
}